// round 6
// baseline (speedup 1.0000x reference)
#include <cuda_runtime.h>
#include <cuda_bf16.h>
#include <cstdint>

namespace {

constexpr int CB = 16;        // codebooks
constexpr int KC = 256;       // codes per codebook
constexpr float BOUND = 0.04419417382415922f;        // 1/sqrt(512)
constexpr float QX = 127.0f / 4.0f;                  // x quant scale
constexpr float SW_INV = 127.0f / BOUND;             // w quant scale
constexpr float SXW = (4.0f / 127.0f) * (BOUND / 127.0f);  // combined dequant
constexpr int OFF_INT = 1 << 22;

// X smem: row-major int8, padded stride 528B (132 words; banks 4r+tig tile 32)
constexpr int XSTRIDE = 528;
constexpr int SM_A    = 0;             // 128 * 528 = 67584
constexpr int SM_W    = 67584;         // W int8 frag double buffer: 2 * 8KB
constexpr int SM_BI   = 83968;         // 4096 u32 bias_int
constexpr int SM_T    = 100352;        // 4096 f32 t
constexpr int SM_PAIR = 116736;        // 16 cb * 128 rows u32
constexpr int SM_RED  = 124928;
constexpr int SMEM_TOTAL = 125056;

__device__ float g_E, g_S;
__device__ int g_cnt;
__device__ float g_t[CB * KC];
__device__ uint32_t g_biasInt[CB * KC];
__device__ uint2 g_WfragI[CB * 1024];   // [cb][ntile 0..31][lane] int8 B frags

__device__ __forceinline__ uint32_t smem_u32(const void* p) {
    uint32_t a;
    asm("{ .reg .u64 t; cvta.to.shared.u64 t, %1; cvt.u32.u64 %0, t; }" : "=r"(a) : "l"(p));
    return a;
}
__device__ __forceinline__ int q8(float f, float sc) {
    int v = __float2int_rn(f * sc);
    return ::min(127, ::max(-127, v));
}
__device__ __forceinline__ uint32_t pack4(int a, int b, int c, int d) {
    return (uint32_t)(a & 255) | ((uint32_t)(b & 255) << 8)
         | ((uint32_t)(c & 255) << 16) | ((uint32_t)(d & 255) << 24);
}
// D = A(16x32 s8) * B(32x8 s8) + C(s32), C = {c0,c1,c0,c1}
__device__ __forceinline__ void imma(int& d0, int& d1, int& d2, int& d3,
                                     uint32_t a0, uint32_t a1, uint32_t a2, uint32_t a3,
                                     uint32_t b0, uint32_t b1, uint32_t c0, uint32_t c1) {
    asm volatile(
        "mma.sync.aligned.m16n8k32.row.col.s32.s8.s8.s32 "
        "{%0,%1,%2,%3}, {%4,%5,%6,%7}, {%8,%9}, {%10,%11,%10,%11};"
        : "=r"(d0), "=r"(d1), "=r"(d2), "=r"(d3)
        : "r"(a0), "r"(a1), "r"(a2), "r"(a3), "r"(b0), "r"(b1),
          "r"(c0), "r"(c1));
}
__device__ __forceinline__ void cpasync16(uint32_t daddr, const void* g) {
    asm volatile("cp.async.cg.shared.global [%0], [%1], 16;" :: "r"(daddr), "l"(g) : "memory");
}

// ---- prep: bid<64 -> W int8 fragments; bid>=64 -> t + bias_int tables ----
__global__ void quant_prep(const float* __restrict__ weight,
                           const float* __restrict__ to_out,
                           const float* __restrict__ bias) {
    if (blockIdx.x == 0 && threadIdx.x == 0) { g_E = 0.0f; g_S = 0.0f; g_cnt = 0; }
    if (blockIdx.x < 64) {
        int id = blockIdx.x * 256 + threadIdx.x;   // 16384
        int cb = id >> 10, rem = id & 1023;
        int nt = rem >> 5, lane = rem & 31;
        int n = nt * 8 + (lane >> 2), tig = lane & 3;
        const float* wr = weight + ((size_t)(cb * KC + n)) * 512 + cb * 32;
        uint2 o;
        o.x = pack4(q8(wr[4 * tig], SW_INV),      q8(wr[4 * tig + 1], SW_INV),
                    q8(wr[4 * tig + 2], SW_INV),  q8(wr[4 * tig + 3], SW_INV));
        o.y = pack4(q8(wr[16 + 4 * tig], SW_INV), q8(wr[17 + 4 * tig], SW_INV),
                    q8(wr[18 + 4 * tig], SW_INV), q8(wr[19 + 4 * tig], SW_INV));
        g_WfragI[id] = o;
    } else {
        int r = (blockIdx.x - 64) * 8 + (threadIdx.x >> 5);
        int lane = threadIdx.x & 31;
        if (r < CB * KC) {
            int c = r >> 8;
            float v = to_out[(size_t)r * 512 + c * 32 + lane];
            float s = v * v;
            #pragma unroll
            for (int o = 16; o; o >>= 1) s += __shfl_xor_sync(0xffffffffu, s, o);
            if (lane == 0) {
                g_t[r] = s + 2.0f * bias[r];
                g_biasInt[r] = (uint32_t)(__float2int_rn(bias[r] / SXW) + OFF_INT);
            }
        }
    }
}

// ---- main: grid 128 x 512. warp = (row-pair p: 32 rows, code-quarter nq: 64) ----
__global__ __launch_bounds__(512, 1)
void quant_main(const float* __restrict__ x,
                float* __restrict__ out) {
    extern __shared__ char smem[];
    const uint32_t sb = smem_u32(smem);
    const int tid = threadIdx.x;
    const int lane = tid & 31, w = tid >> 5, tig = lane & 3;
    const int p = w & 3, nq = w >> 2;

    uint32_t* biS = (uint32_t*)(smem + SM_BI);
    float* tS = (float*)(smem + SM_T);
    uint32_t* pair = (uint32_t*)(smem + SM_PAIR);

    // phase 0a: persistent tables + zero pairbuf
    #pragma unroll
    for (int j = 0; j < 8; j++) {
        int i = j * 512 + tid;
        biS[i] = g_biasInt[i];
        tS[i] = g_t[i];
    }
    #pragma unroll
    for (int j = 0; j < 4; j++) pair[j * 512 + tid] = 0u;

    // phase 0b: X -> int8 row-major smem + sum(x^2)
    float localS = 0.0f;
    {
        const float4* xg = (const float4*)x + (size_t)blockIdx.x * 128 * 128;
        #pragma unroll 8
        for (int it = 0; it < 32; it++) {
            int i = it * 512 + tid;
            float4 v = xg[i];
            localS += v.x * v.x + v.y * v.y + v.z * v.z + v.w * v.w;
            uint32_t b = pack4(q8(v.x, QX), q8(v.y, QX), q8(v.z, QX), q8(v.w, QX));
            int row = i >> 7, chunk = i & 127;
            *(uint32_t*)(smem + SM_A + row * XSTRIDE + chunk * 4) = b;
        }
    }

    // prefetch W for cb 0 (8KB: 512 lines of 16B)
    cpasync16(sb + SM_W + tid * 16, (const char*)g_WfragI + tid * 16);
    asm volatile("cp.async.commit_group;" ::: "memory");

    // A byte offsets: a0 @ (p*32 + lane>>2, k byte 4*tig); +8/+16/+24 rows; +16B
    const char* aBase = smem + SM_A
        + (size_t)((p * 32 + (lane >> 2)) * XSTRIDE + 4 * tig);
    float lE = 0.0f;

    for (int cb = 0; cb < CB; cb++) {
        const int s = cb & 1;
        __syncthreads();
        if (cb + 1 < CB) {
            cpasync16(sb + SM_W + (s ^ 1) * 8192 + tid * 16,
                      (const char*)(g_WfragI + (cb + 1) * 1024) + tid * 16);
            asm volatile("cp.async.commit_group;" ::: "memory");
            asm volatile("cp.async.wait_group 1;" ::: "memory");
        } else {
            asm volatile("cp.async.wait_group 0;" ::: "memory");
        }
        __syncthreads();

        // staggered epilogue: nq==0 warps consume pairbuf[cb-1]
        if (nq == 0 && cb > 0) {
            uint32_t key = pair[(cb - 1) * 128 + p * 32 + lane];
            float sv = (float)((int)(key >> 8) - OFF_INT) * SXW;
            lE += tS[(cb - 1) * 256 + (int)(key & 255u)] - 2.0f * sv;
        }

        // A fragments: two m16 blocks, conflict-free LDS.32
        const char* aC = aBase + cb * 32;
        const uint32_t c0 = *(const uint32_t*)(aC);
        const uint32_t c1 = *(const uint32_t*)(aC + 8 * XSTRIDE);
        const uint32_t c2 = *(const uint32_t*)(aC + 16);
        const uint32_t c3 = *(const uint32_t*)(aC + 8 * XSTRIDE + 16);
        const uint32_t e0 = *(const uint32_t*)(aC + 16 * XSTRIDE);
        const uint32_t e1 = *(const uint32_t*)(aC + 24 * XSTRIDE);
        const uint32_t e2 = *(const uint32_t*)(aC + 16 * XSTRIDE + 16);
        const uint32_t e3 = *(const uint32_t*)(aC + 24 * XSTRIDE + 16);

        const uint2* bB = (const uint2*)(smem + SM_W + s * 8192) + nq * 256 + lane;
        const uint2* biP = (const uint2*)biS + cb * 128 + nq * 32 + tig;

        uint32_t v0 = 0u, v1 = 0u, v2 = 0u, v3 = 0u;
        #pragma unroll 4
        for (int j = 0; j < 8; j++) {
            uint2 bq = bB[j * 32];
            uint2 bi = biP[j * 4];
            int d0, d1, d2, d3, f0, f1, f2, f3;
            imma(d0, d1, d2, d3, c0, c1, c2, c3, bq.x, bq.y, bi.x, bi.y);
            imma(f0, f1, f2, f3, e0, e1, e2, e3, bq.x, bq.y, bi.x, bi.y);
            uint32_t n0 = (uint32_t)(nq * 64 + j * 8) + 2u * (uint32_t)tig;
            v0 = max(v0, (uint32_t)d0 * 256u + n0);
            v0 = max(v0, (uint32_t)d1 * 256u + n0 + 1u);
            v1 = max(v1, (uint32_t)d2 * 256u + n0);
            v1 = max(v1, (uint32_t)d3 * 256u + n0 + 1u);
            v2 = max(v2, (uint32_t)f0 * 256u + n0);
            v2 = max(v2, (uint32_t)f1 * 256u + n0 + 1u);
            v3 = max(v3, (uint32_t)f2 * 256u + n0);
            v3 = max(v3, (uint32_t)f3 * 256u + n0 + 1u);
        }
        #pragma unroll
        for (int o = 1; o < 4; o <<= 1) {
            v0 = max(v0, __shfl_xor_sync(0xffffffffu, v0, o));
            v1 = max(v1, __shfl_xor_sync(0xffffffffu, v1, o));
            v2 = max(v2, __shfl_xor_sync(0xffffffffu, v2, o));
            v3 = max(v3, __shfl_xor_sync(0xffffffffu, v3, o));
        }
        if (tig == 0) {
            int g = lane >> 2;
            uint32_t* pb = pair + cb * 128 + p * 32;
            atomicMax(pb + g, v0);
            atomicMax(pb + 8 + g, v1);
            atomicMax(pb + 16 + g, v2);
            atomicMax(pb + 24 + g, v3);
        }
    }
    __syncthreads();
    if (nq == 0) {   // final cb epilogue
        uint32_t key = pair[15 * 128 + p * 32 + lane];
        float sv = (float)((int)(key >> 8) - OFF_INT) * SXW;
        lE += tS[15 * 256 + (int)(key & 255u)] - 2.0f * sv;
    }

    // block reduction + global accumulate; last CTA finalizes
    #pragma unroll
    for (int o = 16; o; o >>= 1) {
        lE += __shfl_xor_sync(0xffffffffu, lE, o);
        localS += __shfl_xor_sync(0xffffffffu, localS, o);
    }
    float* red = (float*)(smem + SM_RED);
    if (lane == 0) { red[w] = lE; red[16 + w] = localS; }
    __syncthreads();
    if (tid == 0) {
        float e = 0.0f, ss = 0.0f;
        #pragma unroll
        for (int j = 0; j < 16; j++) { e += red[j]; ss += red[16 + j]; }
        atomicAdd(&g_E, e);
        atomicAdd(&g_S, ss);
        __threadfence();
        if (atomicAdd(&g_cnt, 1) == 127) {
            float E = atomicAdd(&g_E, 0.0f);
            float S = atomicAdd(&g_S, 0.0f);
            out[0] = (E + S) / (S + 1e-20f);
        }
    }
}

}  // namespace

extern "C" void kernel_launch(void* const* d_in, const int* in_sizes, int n_in,
                              void* d_out, int out_size) {
    const float* x      = (const float*)d_in[0];
    const float* weight = (const float*)d_in[1];
    const float* bias   = (const float*)d_in[2];
    const float* to_out = (const float*)d_in[3];

    cudaFuncSetAttribute(quant_main, cudaFuncAttributeMaxDynamicSharedMemorySize,
                         SMEM_TOTAL);
    quant_prep<<<576, 256>>>(weight, to_out, bias);
    quant_main<<<128, 512, SMEM_TOTAL>>>(x, (float*)d_out);
}

// round 7
// speedup vs baseline: 1.4645x; 1.4645x over previous
#include <cuda_runtime.h>
#include <cuda_bf16.h>
#include <cuda_fp16.h>
#include <cstdint>

namespace {

constexpr int CB = 16;        // codebooks
constexpr int KC = 256;       // codes per codebook
constexpr int ROWS = 64;      // rows per CTA
constexpr float OFFSET = 8.0f;

// X smem: row-major bf16, padded stride 1040B (65*16, odd -> ldmatrix conflict-free)
constexpr int XSTRIDE = 1040;
constexpr int SM_A    = 0;             // 64 * 1040 = 66560
constexpr int SM_W    = 66560;         // W frag double buffer: 2 * 16KB
constexpr int SM_B2   = 99328;         // 2048 u32 half2 bias pairs (b+8)
constexpr int SM_PAIR = 107520;        // 16 cb * 64 rows u32
constexpr int SM_RED  = 111616;        // 32 f32
constexpr int SMEM_TOTAL = 111744;

__device__ float g_E, g_S;
__device__ int g_cnt;
__device__ float g_t[CB * KC];
__device__ uint32_t g_bias2[CB * KC / 2];   // half2(b[2i]+8, b[2i+1]+8)
__device__ uint4 g_Wfrag[CB * 1024];        // [cb][nt 0..31][lane] bf16 B frags

__device__ __forceinline__ uint32_t smem_u32(const void* p) {
    uint32_t a;
    asm("{ .reg .u64 t; cvta.to.shared.u64 t, %1; cvt.u32.u64 %0, t; }" : "=r"(a) : "l"(p));
    return a;
}
__device__ __forceinline__ uint32_t pack_bf16(float lo, float hi) {
    uint32_t r;
    asm("cvt.rn.bf16x2.f32 %0, %1, %2;" : "=r"(r) : "f"(hi), "f"(lo));
    return r;
}
__device__ __forceinline__ void mma_init(float& d0, float& d1, float& d2, float& d3,
                                         uint32_t a0, uint32_t a1, uint32_t a2, uint32_t a3,
                                         uint32_t b0, uint32_t b1, float c0, float c1) {
    asm volatile(
        "mma.sync.aligned.m16n8k16.row.col.f32.bf16.bf16.f32 "
        "{%0,%1,%2,%3}, {%4,%5,%6,%7}, {%8,%9}, {%10,%11,%10,%11};"
        : "=f"(d0), "=f"(d1), "=f"(d2), "=f"(d3)
        : "r"(a0), "r"(a1), "r"(a2), "r"(a3), "r"(b0), "r"(b1), "f"(c0), "f"(c1));
}
__device__ __forceinline__ void mma_acc(float& d0, float& d1, float& d2, float& d3,
                                        uint32_t a0, uint32_t a1, uint32_t a2, uint32_t a3,
                                        uint32_t b0, uint32_t b1) {
    asm volatile(
        "mma.sync.aligned.m16n8k16.row.col.f32.bf16.bf16.f32 "
        "{%0,%1,%2,%3}, {%4,%5,%6,%7}, {%8,%9}, {%0,%1,%2,%3};"
        : "+f"(d0), "+f"(d1), "+f"(d2), "+f"(d3)
        : "r"(a0), "r"(a1), "r"(a2), "r"(a3), "r"(b0), "r"(b1));
}
__device__ __forceinline__ void ldmatrix_x4(uint32_t& r0, uint32_t& r1,
                                            uint32_t& r2, uint32_t& r3, uint32_t addr) {
    asm volatile("ldmatrix.sync.aligned.m8n8.x4.shared.b16 {%0,%1,%2,%3}, [%4];"
                 : "=r"(r0), "=r"(r1), "=r"(r2), "=r"(r3) : "r"(addr));
}
__device__ __forceinline__ void cpasync16(uint32_t daddr, const void* g) {
    asm volatile("cp.async.cg.shared.global [%0], [%1], 16;" :: "r"(daddr), "l"(g) : "memory");
}

// ---- prep: bid<64 -> W fragments; bid>=64 -> t table + bias2 pairs ----
__global__ void quant_prep(const float* __restrict__ weight,
                           const float* __restrict__ to_out,
                           const float* __restrict__ bias) {
    if (blockIdx.x == 0 && threadIdx.x == 0) { g_E = 0.0f; g_S = 0.0f; g_cnt = 0; }
    if (blockIdx.x < 64) {
        int id = blockIdx.x * 256 + threadIdx.x;   // 16384
        int cb = id >> 10, rem = id & 1023;
        int nt = rem >> 5, lane = rem & 31;
        int n = nt * 8 + (lane >> 2), tig = lane & 3;
        const float* wr = weight + ((size_t)(cb * KC + n)) * 512 + cb * 32;
        uint4 o;
        o.x = pack_bf16(wr[2 * tig],      wr[2 * tig + 1]);
        o.y = pack_bf16(wr[2 * tig + 8],  wr[2 * tig + 9]);
        o.z = pack_bf16(wr[2 * tig + 16], wr[2 * tig + 17]);
        o.w = pack_bf16(wr[2 * tig + 24], wr[2 * tig + 25]);
        g_Wfrag[id] = o;
    } else {
        int r = (blockIdx.x - 64) * 8 + (threadIdx.x >> 5);
        int lane = threadIdx.x & 31;
        if (r < CB * KC) {
            int c = r >> 8;
            float v = to_out[(size_t)r * 512 + c * 32 + lane];
            float s = v * v;
            #pragma unroll
            for (int o = 16; o; o >>= 1) s += __shfl_xor_sync(0xffffffffu, s, o);
            if (lane == 0) {
                // effective bias = f16(b + OFFSET) - OFFSET, matching mainloop C-init
                float beff = __half2float(__float2half(bias[r] + OFFSET)) - OFFSET;
                g_t[r] = s + 2.0f * beff;
            }
            if (lane == 1 && !(r & 1)) {
                __half2 h = __floats2half2_rn(bias[r] + OFFSET, bias[r + 1] + OFFSET);
                g_bias2[r >> 1] = *(uint32_t*)&h;
            }
        }
    }
}

// ---- main: grid 256 x 512, 2 CTAs/SM. warp = (row-half p: 32, code-eighth nq: 32) ----
__global__ __launch_bounds__(512, 2)
void quant_main(const float* __restrict__ x,
                float* __restrict__ out) {
    extern __shared__ char smem[];
    const uint32_t sb = smem_u32(smem);
    const int tid = threadIdx.x;
    const int lane = tid & 31, w = tid >> 5, tig = lane & 3;
    const int p = w & 1, nq = w >> 1;

    uint32_t* b2S = (uint32_t*)(smem + SM_B2);
    uint32_t* pair = (uint32_t*)(smem + SM_PAIR);

    // phase 0a: bias2 table + zero pairbuf
    #pragma unroll
    for (int j = 0; j < 4; j++) {
        int i = j * 512 + tid;
        b2S[i] = g_bias2[i];
    }
    #pragma unroll
    for (int j = 0; j < 2; j++) pair[j * 512 + tid] = 0u;

    // phase 0b: X -> row-major bf16 smem + sum(x^2)
    float localS = 0.0f;
    {
        const float4* xg = (const float4*)x + (size_t)blockIdx.x * ROWS * 128;
        #pragma unroll 4
        for (int it = 0; it < 16; it++) {
            int i = it * 512 + tid;
            float4 v = xg[i];
            localS += v.x * v.x + v.y * v.y + v.z * v.z + v.w * v.w;
            int row = i >> 7, chunk = i & 127;
            uint2 st;
            st.x = pack_bf16(v.x, v.y);
            st.y = pack_bf16(v.z, v.w);
            *(uint2*)(smem + SM_A + row * XSTRIDE + chunk * 8) = st;
        }
    }

    // prefetch W for cb 0 (1024 uint4 lines, 2 per thread)
    cpasync16(sb + SM_W + tid * 16, g_Wfrag + tid);
    cpasync16(sb + SM_W + (tid + 512) * 16, g_Wfrag + tid + 512);
    asm volatile("cp.async.commit_group;" ::: "memory");

    const uint32_t a_base = sb + SM_A
        + (uint32_t)((p * 32 + (lane & 15)) * XSTRIDE + (lane >> 4) * 16);
    float lE = 0.0f;

    for (int cb = 0; cb < CB; cb++) {
        const int s = cb & 1;
        __syncthreads();   // prev compute done; pairbuf[cb-1] complete; buf s^1 free
        if (cb + 1 < CB) {
            uint32_t d = sb + SM_W + (s ^ 1) * 16384;
            const uint4* src = g_Wfrag + (cb + 1) * 1024;
            cpasync16(d + tid * 16, src + tid);
            cpasync16(d + (tid + 512) * 16, src + tid + 512);
            asm volatile("cp.async.commit_group;" ::: "memory");
            asm volatile("cp.async.wait_group 1;" ::: "memory");
        } else {
            asm volatile("cp.async.wait_group 0;" ::: "memory");
        }
        __syncthreads();   // buf s visible

        // staggered epilogue: nq==0 warps consume pairbuf[cb-1]
        if (nq == 0 && cb > 0) {
            uint32_t key = pair[(cb - 1) * 64 + p * 32 + lane];
            float sv = __uint_as_float(key & 0xFFFFFF00u) - OFFSET;
            lE += __ldg(&g_t[(cb - 1) * 256 + (int)(key & 255u)]) - 2.0f * sv;
        }

        // A fragments: two m16 blocks x two k-steps
        uint32_t c0, c1, c2, c3, c4, c5, c6, c7;
        uint32_t e0, e1, e2, e3, e4, e5, e6, e7;
        ldmatrix_x4(c0, c1, c2, c3, a_base + cb * 64);
        ldmatrix_x4(c4, c5, c6, c7, a_base + cb * 64 + 32);
        ldmatrix_x4(e0, e1, e2, e3, a_base + 16 * XSTRIDE + cb * 64);
        ldmatrix_x4(e4, e5, e6, e7, a_base + 16 * XSTRIDE + cb * 64 + 32);

        const uint4* bB = (const uint4*)(smem + SM_W + s * 16384) + nq * 128 + lane;
        const uint32_t* biP = b2S + cb * 128 + nq * 16 + tig;

        uint32_t v0 = 0u, v1 = 0u, v2 = 0u, v3 = 0u;
        #pragma unroll
        for (int j = 0; j < 4; j++) {
            uint4 bq = bB[j * 32];
            __half2 bh = *(const __half2*)(biP + j * 4);
            float bv0 = __half2float(__low2half(bh));
            float bv1 = __half2float(__high2half(bh));
            float d0, d1, d2, d3, f0, f1, f2, f3;
            mma_init(d0, d1, d2, d3, c0, c1, c2, c3, bq.x, bq.y, bv0, bv1);
            mma_acc (d0, d1, d2, d3, c4, c5, c6, c7, bq.z, bq.w);
            mma_init(f0, f1, f2, f3, e0, e1, e2, e3, bq.x, bq.y, bv0, bv1);
            mma_acc (f0, f1, f2, f3, e4, e5, e6, e7, bq.z, bq.w);
            uint32_t n0 = (uint32_t)(nq * 32 + j * 8) + 2u * (uint32_t)tig;
            v0 = max(v0, (__float_as_uint(d0) & 0xFFFFFF00u) | n0);
            v0 = max(v0, (__float_as_uint(d1) & 0xFFFFFF00u) | (n0 + 1u));
            v1 = max(v1, (__float_as_uint(d2) & 0xFFFFFF00u) | n0);
            v1 = max(v1, (__float_as_uint(d3) & 0xFFFFFF00u) | (n0 + 1u));
            v2 = max(v2, (__float_as_uint(f0) & 0xFFFFFF00u) | n0);
            v2 = max(v2, (__float_as_uint(f1) & 0xFFFFFF00u) | (n0 + 1u));
            v3 = max(v3, (__float_as_uint(f2) & 0xFFFFFF00u) | n0);
            v3 = max(v3, (__float_as_uint(f3) & 0xFFFFFF00u) | (n0 + 1u));
        }
        #pragma unroll
        for (int o = 1; o < 4; o <<= 1) {
            v0 = max(v0, __shfl_xor_sync(0xffffffffu, v0, o));
            v1 = max(v1, __shfl_xor_sync(0xffffffffu, v1, o));
            v2 = max(v2, __shfl_xor_sync(0xffffffffu, v2, o));
            v3 = max(v3, __shfl_xor_sync(0xffffffffu, v3, o));
        }
        if (tig == 0) {
            int g = lane >> 2;
            uint32_t* pb = pair + cb * 64 + p * 32;
            atomicMax(pb + g, v0);
            atomicMax(pb + 8 + g, v1);
            atomicMax(pb + 16 + g, v2);
            atomicMax(pb + 24 + g, v3);
        }
    }
    __syncthreads();
    if (nq == 0) {   // final cb epilogue
        uint32_t key = pair[15 * 64 + p * 32 + lane];
        float sv = __uint_as_float(key & 0xFFFFFF00u) - OFFSET;
        lE += __ldg(&g_t[15 * 256 + (int)(key & 255u)]) - 2.0f * sv;
    }

    // block reduction + global accumulate; last CTA finalizes
    #pragma unroll
    for (int o = 16; o; o >>= 1) {
        lE += __shfl_xor_sync(0xffffffffu, lE, o);
        localS += __shfl_xor_sync(0xffffffffu, localS, o);
    }
    float* red = (float*)(smem + SM_RED);
    if (lane == 0) { red[w] = lE; red[16 + w] = localS; }
    __syncthreads();
    if (tid == 0) {
        float e = 0.0f, ss = 0.0f;
        #pragma unroll
        for (int j = 0; j < 16; j++) { e += red[j]; ss += red[16 + j]; }
        atomicAdd(&g_E, e);
        atomicAdd(&g_S, ss);
        __threadfence();
        if (atomicAdd(&g_cnt, 1) == 255) {
            float E = atomicAdd(&g_E, 0.0f);
            float S = atomicAdd(&g_S, 0.0f);
            out[0] = (E + S) / (S + 1e-20f);
        }
    }
}

}  // namespace

extern "C" void kernel_launch(void* const* d_in, const int* in_sizes, int n_in,
                              void* d_out, int out_size) {
    const float* x      = (const float*)d_in[0];
    const float* weight = (const float*)d_in[1];
    const float* bias   = (const float*)d_in[2];
    const float* to_out = (const float*)d_in[3];

    cudaFuncSetAttribute(quant_main, cudaFuncAttributeMaxDynamicSharedMemorySize,
                         SMEM_TOTAL);
    quant_prep<<<576, 256>>>(weight, to_out, bias);
    quant_main<<<256, 512, SMEM_TOTAL>>>(x, (float*)d_out);
}

// round 8
// speedup vs baseline: 1.5581x; 1.0640x over previous
#include <cuda_runtime.h>
#include <cuda_bf16.h>
#include <cuda_fp16.h>
#include <cstdint>

namespace {

constexpr int CB = 16;        // codebooks
constexpr int KC = 256;       // codes per codebook
constexpr int ROWS = 128;     // rows per CTA
constexpr float OFFSET = 8.0f;

// X smem: row-major bf16, padded stride 1040B (odd 16B units -> conflict-free ldmatrix)
constexpr int XSTRIDE = 1040;
constexpr int SM_A   = 0;              // 128 * 1040 = 133120
constexpr int SM_B2  = 133120;         // 2048 u32 half2 bias pairs (b+8)  (8KB)
constexpr int SM_T   = 141312;         // 4096 f32 t                      (16KB)
constexpr int SM_PB  = 157696;         // 16 warps * 128 rows u32         (8KB)
constexpr int SM_RED = 165888;         // 32 f32
constexpr int SMEM_TOTAL = 166016;

__device__ float g_E, g_S;
__device__ int g_cnt;
__device__ float g_t[CB * KC];
__device__ uint32_t g_bias2[CB * KC / 2];   // half2(b[2i]+8, b[2i+1]+8)
__device__ uint4 g_Wfrag[CB * 1024];        // [cb][nt 0..31][lane] bf16 B frags

__device__ __forceinline__ uint32_t smem_u32(const void* p) {
    uint32_t a;
    asm("{ .reg .u64 t; cvta.to.shared.u64 t, %1; cvt.u32.u64 %0, t; }" : "=r"(a) : "l"(p));
    return a;
}
__device__ __forceinline__ uint32_t pack_bf16(float lo, float hi) {
    uint32_t r;
    asm("cvt.rn.bf16x2.f32 %0, %1, %2;" : "=r"(r) : "f"(hi), "f"(lo));
    return r;
}
__device__ __forceinline__ void mma_init(float& d0, float& d1, float& d2, float& d3,
                                         uint32_t a0, uint32_t a1, uint32_t a2, uint32_t a3,
                                         uint32_t b0, uint32_t b1, float c0, float c1) {
    asm volatile(
        "mma.sync.aligned.m16n8k16.row.col.f32.bf16.bf16.f32 "
        "{%0,%1,%2,%3}, {%4,%5,%6,%7}, {%8,%9}, {%10,%11,%10,%11};"
        : "=f"(d0), "=f"(d1), "=f"(d2), "=f"(d3)
        : "r"(a0), "r"(a1), "r"(a2), "r"(a3), "r"(b0), "r"(b1), "f"(c0), "f"(c1));
}
__device__ __forceinline__ void mma_acc(float& d0, float& d1, float& d2, float& d3,
                                        uint32_t a0, uint32_t a1, uint32_t a2, uint32_t a3,
                                        uint32_t b0, uint32_t b1) {
    asm volatile(
        "mma.sync.aligned.m16n8k16.row.col.f32.bf16.bf16.f32 "
        "{%0,%1,%2,%3}, {%4,%5,%6,%7}, {%8,%9}, {%0,%1,%2,%3};"
        : "+f"(d0), "+f"(d1), "+f"(d2), "+f"(d3)
        : "r"(a0), "r"(a1), "r"(a2), "r"(a3), "r"(b0), "r"(b1));
}
__device__ __forceinline__ void ldmatrix_x4(uint32_t& r0, uint32_t& r1,
                                            uint32_t& r2, uint32_t& r3, uint32_t addr) {
    asm volatile("ldmatrix.sync.aligned.m8n8.x4.shared.b16 {%0,%1,%2,%3}, [%4];"
                 : "=r"(r0), "=r"(r1), "=r"(r2), "=r"(r3) : "r"(addr));
}

// ---- prep: bid<64 -> W fragments; bid>=64 -> t table + bias2 pairs ----
__global__ void quant_prep(const float* __restrict__ weight,
                           const float* __restrict__ to_out,
                           const float* __restrict__ bias) {
    if (blockIdx.x == 0 && threadIdx.x == 0) { g_E = 0.0f; g_S = 0.0f; g_cnt = 0; }
    if (blockIdx.x < 64) {
        int id = blockIdx.x * 256 + threadIdx.x;   // 16384
        int cb = id >> 10, rem = id & 1023;
        int nt = rem >> 5, lane = rem & 31;
        int n = nt * 8 + (lane >> 2), tig = lane & 3;
        const float* wr = weight + ((size_t)(cb * KC + n)) * 512 + cb * 32;
        uint4 o;
        o.x = pack_bf16(wr[2 * tig],      wr[2 * tig + 1]);
        o.y = pack_bf16(wr[2 * tig + 8],  wr[2 * tig + 9]);
        o.z = pack_bf16(wr[2 * tig + 16], wr[2 * tig + 17]);
        o.w = pack_bf16(wr[2 * tig + 24], wr[2 * tig + 25]);
        g_Wfrag[id] = o;
    } else {
        int r = (blockIdx.x - 64) * 8 + (threadIdx.x >> 5);
        int lane = threadIdx.x & 31;
        if (r < CB * KC) {
            int c = r >> 8;
            float v = to_out[(size_t)r * 512 + c * 32 + lane];
            float s = v * v;
            #pragma unroll
            for (int o = 16; o; o >>= 1) s += __shfl_xor_sync(0xffffffffu, s, o);
            if (lane == 0) {
                // effective bias = f16(b + OFFSET) - OFFSET (matches mainloop C-init)
                float beff = __half2float(__float2half(bias[r] + OFFSET)) - OFFSET;
                g_t[r] = s + 2.0f * beff;
            }
            if (lane == 1 && !(r & 1)) {
                __half2 h = __floats2half2_rn(bias[r] + OFFSET, bias[r + 1] + OFFSET);
                g_bias2[r >> 1] = *(uint32_t*)&h;
            }
        }
    }
}

// ---- main: grid 128 x 512. warp w owns codebook w; zero mainloop barriers ----
__global__ __launch_bounds__(512, 1)
void quant_main(const float* __restrict__ x,
                float* __restrict__ out) {
    extern __shared__ char smem[];
    const uint32_t sb = smem_u32(smem);
    const int tid = threadIdx.x;
    const int lane = tid & 31, w = tid >> 5, tig = lane & 3;
    const int cb = w;

    uint32_t* b2S = (uint32_t*)(smem + SM_B2);
    float* tS = (float*)(smem + SM_T);
    uint32_t* pb = (uint32_t*)(smem + SM_PB) + w * 128;   // warp-private

    // phase 0a: tables
    #pragma unroll
    for (int j = 0; j < 4; j++) b2S[j * 512 + tid] = g_bias2[j * 512 + tid];
    #pragma unroll
    for (int j = 0; j < 8; j++) tS[j * 512 + tid] = g_t[j * 512 + tid];

    // phase 0b: X -> row-major bf16 smem + sum(x^2)
    float localS = 0.0f;
    {
        const float4* xg = (const float4*)x + (size_t)blockIdx.x * ROWS * 128;
        #pragma unroll 4
        for (int it = 0; it < 16; it++) {
            int i = it * 512 + tid;
            float4 v = xg[i];
            localS += v.x * v.x + v.y * v.y + v.z * v.z + v.w * v.w;
            int row = i >> 7, chunk = i & 127;
            uint2 st;
            st.x = pack_bf16(v.x, v.y);
            st.y = pack_bf16(v.z, v.w);
            *(uint2*)(smem + SM_A + row * XSTRIDE + chunk * 8) = st;
        }
    }
    __syncthreads();   // the only block-wide sync before the reduction

    const uint32_t a_base = sb + SM_A
        + (uint32_t)((lane & 15) * XSTRIDE + (lane >> 4) * 16 + cb * 64);
    float lE = 0.0f;
    uint4 B[16];

    // ============ pass 0: codes 0..127 — compute keys, stash to pb ============
    #pragma unroll
    for (int j = 0; j < 16; j++) B[j] = g_Wfrag[cb * 1024 + j * 32 + lane];

    #pragma unroll 1
    for (int blk = 0; blk < 8; blk++) {
        uint32_t c0, c1, c2, c3, c4, c5, c6, c7;
        ldmatrix_x4(c0, c1, c2, c3, a_base + blk * 16 * XSTRIDE);
        ldmatrix_x4(c4, c5, c6, c7, a_base + blk * 16 * XSTRIDE + 32);
        uint32_t v0 = 0u, v1 = 0u;
        #pragma unroll
        for (int j = 0; j < 16; j++) {
            __half2 bh = *(const __half2*)(b2S + cb * 128 + j * 4 + tig);
            float d0, d1, d2, d3;
            mma_init(d0, d1, d2, d3, c0, c1, c2, c3, B[j].x, B[j].y,
                     __half2float(__low2half(bh)), __half2float(__high2half(bh)));
            mma_acc (d0, d1, d2, d3, c4, c5, c6, c7, B[j].z, B[j].w);
            uint32_t n0 = (uint32_t)(j * 8) + 2u * (uint32_t)tig;
            v0 = max(v0, (__float_as_uint(d0) & 0xFFFFFF00u) | n0);
            v0 = max(v0, (__float_as_uint(d1) & 0xFFFFFF00u) | (n0 + 1u));
            v1 = max(v1, (__float_as_uint(d2) & 0xFFFFFF00u) | n0);
            v1 = max(v1, (__float_as_uint(d3) & 0xFFFFFF00u) | (n0 + 1u));
        }
        v0 = max(v0, __shfl_xor_sync(0xffffffffu, v0, 1));
        v0 = max(v0, __shfl_xor_sync(0xffffffffu, v0, 2));
        v1 = max(v1, __shfl_xor_sync(0xffffffffu, v1, 1));
        v1 = max(v1, __shfl_xor_sync(0xffffffffu, v1, 2));
        if (tig == 0) {
            pb[blk * 16 + (lane >> 2)] = v0;
            pb[blk * 16 + 8 + (lane >> 2)] = v1;
        }
    }

    // ============ pass 1: codes 128..255 — combine + t-lookup ============
    #pragma unroll
    for (int j = 0; j < 16; j++) B[j] = g_Wfrag[cb * 1024 + (16 + j) * 32 + lane];

    #pragma unroll 1
    for (int blk = 0; blk < 8; blk++) {
        uint32_t c0, c1, c2, c3, c4, c5, c6, c7;
        ldmatrix_x4(c0, c1, c2, c3, a_base + blk * 16 * XSTRIDE);
        ldmatrix_x4(c4, c5, c6, c7, a_base + blk * 16 * XSTRIDE + 32);
        uint32_t v0 = 0u, v1 = 0u;
        #pragma unroll
        for (int j = 0; j < 16; j++) {
            __half2 bh = *(const __half2*)(b2S + cb * 128 + 64 + j * 4 + tig);
            float d0, d1, d2, d3;
            mma_init(d0, d1, d2, d3, c0, c1, c2, c3, B[j].x, B[j].y,
                     __half2float(__low2half(bh)), __half2float(__high2half(bh)));
            mma_acc (d0, d1, d2, d3, c4, c5, c6, c7, B[j].z, B[j].w);
            uint32_t n0 = 128u + (uint32_t)(j * 8) + 2u * (uint32_t)tig;
            v0 = max(v0, (__float_as_uint(d0) & 0xFFFFFF00u) | n0);
            v0 = max(v0, (__float_as_uint(d1) & 0xFFFFFF00u) | (n0 + 1u));
            v1 = max(v1, (__float_as_uint(d2) & 0xFFFFFF00u) | n0);
            v1 = max(v1, (__float_as_uint(d3) & 0xFFFFFF00u) | (n0 + 1u));
        }
        v0 = max(v0, __shfl_xor_sync(0xffffffffu, v0, 1));
        v0 = max(v0, __shfl_xor_sync(0xffffffffu, v0, 2));
        v1 = max(v1, __shfl_xor_sync(0xffffffffu, v1, 1));
        v1 = max(v1, __shfl_xor_sync(0xffffffffu, v1, 2));
        if (tig == 0) {
            uint32_t k0 = max(v0, pb[blk * 16 + (lane >> 2)]);
            uint32_t k1 = max(v1, pb[blk * 16 + 8 + (lane >> 2)]);
            float s0 = __uint_as_float(k0 & 0xFFFFFF00u) - OFFSET;
            float s1 = __uint_as_float(k1 & 0xFFFFFF00u) - OFFSET;
            lE += (tS[cb * 256 + (int)(k0 & 255u)] - 2.0f * s0)
                + (tS[cb * 256 + (int)(k1 & 255u)] - 2.0f * s1);
        }
    }

    // block reduction + global accumulate; last CTA finalizes
    #pragma unroll
    for (int o = 16; o; o >>= 1) {
        lE += __shfl_xor_sync(0xffffffffu, lE, o);
        localS += __shfl_xor_sync(0xffffffffu, localS, o);
    }
    float* red = (float*)(smem + SM_RED);
    if (lane == 0) { red[w] = lE; red[16 + w] = localS; }
    __syncthreads();
    if (tid == 0) {
        float e = 0.0f, ss = 0.0f;
        #pragma unroll
        for (int j = 0; j < 16; j++) { e += red[j]; ss += red[16 + j]; }
        atomicAdd(&g_E, e);
        atomicAdd(&g_S, ss);
        __threadfence();
        if (atomicAdd(&g_cnt, 1) == 127) {
            float E = atomicAdd(&g_E, 0.0f);
            float S = atomicAdd(&g_S, 0.0f);
            out[0] = (E + S) / (S + 1e-20f);
        }
    }
}

}  // namespace

extern "C" void kernel_launch(void* const* d_in, const int* in_sizes, int n_in,
                              void* d_out, int out_size) {
    const float* x      = (const float*)d_in[0];
    const float* weight = (const float*)d_in[1];
    const float* bias   = (const float*)d_in[2];
    const float* to_out = (const float*)d_in[3];

    cudaFuncSetAttribute(quant_main, cudaFuncAttributeMaxDynamicSharedMemorySize,
                         SMEM_TOTAL);
    quant_prep<<<576, 256>>>(weight, to_out, bias);
    quant_main<<<128, 512, SMEM_TOTAL>>>(x, (float*)d_out);
}